// round 5
// baseline (speedup 1.0000x reference)
#include <cuda_runtime.h>
#include <cuda_fp16.h>
#include <math.h>
#include <stdint.h>

#define H 96
#define W 96
#define HW (H*W)          // 9216
#define CIN 256
#define B 2
#define KK 9
#define GK (CIN*KK)       // 2304
#define GM 256
#define GN HW

// ---------------- scratch (static device allocations) -------------------------
__device__ __half g_colhi[(size_t)B * GK * HW];     // im2col hi plane [b][k][p]
__device__ __half g_collo[(size_t)B * GK * HW];     // im2col lo plane
__device__ float g_om[(size_t)B * 27 * HW];
__device__ float g_om_part[4ull * B * 27 * HW];
__device__ float g_h[(size_t)B * CIN * HW];
__device__ __half g_whi[(size_t)GM * GK];           // W hi [o][k]
__device__ __half g_wlo[(size_t)GM * GK];           // W lo

// ---------------- helpers ------------------------------------------------------
__device__ __forceinline__ uint32_t sm_u32(const void* p) {
    uint32_t a;
    asm("{ .reg .u64 t; cvta.to.shared.u64 t, %1; cvt.u32.u64 %0, t; }" : "=r"(a) : "l"(p));
    return a;
}
__device__ __forceinline__ void cpasync16(uint32_t dst, const void* src) {
    asm volatile("cp.async.cg.shared.global [%0], [%1], 16;" :: "r"(dst), "l"(src));
}
#define CP_COMMIT() asm volatile("cp.async.commit_group;" ::: "memory")
#define CP_WAIT1()  asm volatile("cp.async.wait_group 1;" ::: "memory")

#define LDSM_X4(r0, r1, r2, r3, addr) \
    asm volatile("ldmatrix.sync.aligned.m8n8.x4.shared.b16 {%0,%1,%2,%3}, [%4];" \
        : "=r"(r0), "=r"(r1), "=r"(r2), "=r"(r3) : "r"(addr))
#define LDSM_X4_T(r0, r1, r2, r3, addr) \
    asm volatile("ldmatrix.sync.aligned.m8n8.x4.trans.shared.b16 {%0,%1,%2,%3}, [%4];" \
        : "=r"(r0), "=r"(r1), "=r"(r2), "=r"(r3) : "r"(addr))

#define MMA_F16(d, a, bb) \
    asm volatile("mma.sync.aligned.m16n8k16.row.col.f32.f16.f16.f32 " \
        "{%0,%1,%2,%3}, {%4,%5,%6,%7}, {%8,%9}, {%0,%1,%2,%3};" \
        : "+f"((d)[0]), "+f"((d)[1]), "+f"((d)[2]), "+f"((d)[3]) \
        : "r"((a)[0]), "r"((a)[1]), "r"((a)[2]), "r"((a)[3]), \
          "r"((bb)[0]), "r"((bb)[1]))

// ---------------- offset conv (SMEM-tiled): grid (36,4,B), block 256 ----------
__global__ void offset_conv_kernel(const float* __restrict__ x,
                                   const float* __restrict__ w_off,
                                   float* __restrict__ om_part) {
    int b = blockIdx.z, chunk = blockIdx.y, tile = blockIdx.x;
    int h0 = (tile / 6) * 16, w0 = (tile % 6) * 16;
    int ty = threadIdx.x >> 4, tx = threadIdx.x & 15;

    float acc[27];
#pragma unroll
    for (int i = 0; i < 27; i++) acc[i] = 0.f;

    __shared__ float ws[243];
    __shared__ float xt[18 * 18];
    const float* xb = x + (size_t)b * CIN * HW;
    int c0 = chunk * 64;
    for (int c = c0; c < c0 + 64; c++) {
        __syncthreads();
        if (threadIdx.x < 243) {
            int oc = threadIdx.x / 9, k = threadIdx.x % 9;
            ws[threadIdx.x] = w_off[((size_t)oc * CIN + c) * 9 + k];
        }
        const float* xc = xb + (size_t)c * HW;
        for (int idx = threadIdx.x; idx < 324; idx += 256) {
            int yy = h0 - 1 + idx / 18, xx = w0 - 1 + idx % 18;
            xt[idx] = (yy >= 0 && yy < H && xx >= 0 && xx < W) ? xc[yy * W + xx] : 0.f;
        }
        __syncthreads();
        float xv[9];
#pragma unroll
        for (int k = 0; k < 9; k++)
            xv[k] = xt[(ty + k / 3) * 18 + tx + k % 3];
#pragma unroll
        for (int oc = 0; oc < 27; oc++)
#pragma unroll
            for (int k = 0; k < 9; k++)
                acc[oc] = fmaf(ws[oc * 9 + k], xv[k], acc[oc]);
    }
    int h = h0 + ty, w = w0 + tx;
    float* dst = om_part + ((size_t)chunk * B * 27 + (size_t)b * 27) * HW + h * W + w;
#pragma unroll
    for (int oc = 0; oc < 27; oc++) dst[(size_t)oc * HW] = acc[oc];
}

__global__ void reduce_om_kernel(const float* __restrict__ part,
                                 const float* __restrict__ b_off,
                                 float* __restrict__ om) {
    int i = blockIdx.x * 256 + threadIdx.x;
    const int N = B * 27 * HW;
    int oc = (i / HW) % 27;
    float s = b_off[oc];
#pragma unroll
    for (int j = 0; j < 4; j++) s += part[(size_t)j * N + i];
    om[i] = s;
}

// ---------------- deformable im2col -> fp16 hi/lo planes ----------------------
__global__ void sample_kernel(const float* __restrict__ x,
                              const float* __restrict__ om,
                              __half* __restrict__ chi,
                              __half* __restrict__ clo) {
    int b = blockIdx.z;
    int k = blockIdx.y;
    int p = blockIdx.x * 256 + threadIdx.x;
    int h = p / W, w = p % W;

    const float* omb = om + (size_t)b * 27 * HW;
    float dy = omb[(size_t)(2 * k) * HW + p];
    float dx = omb[(size_t)(2 * k + 1) * HW + p];
    float m  = omb[(size_t)(18 + k) * HW + p];
    m = 1.f / (1.f + __expf(-m));

    float ys = (float)(h + k / 3 - 1) + dy;
    float xs = (float)(w + k % 3 - 1) + dx;
    float y0f = floorf(ys), x0f = floorf(xs);
    int y0 = (int)y0f, x0 = (int)x0f;
    int y1 = y0 + 1, x1 = x0 + 1;
    float wy1 = ys - y0f, wx1 = xs - x0f;
    float wy0 = 1.f - wy1, wx0 = 1.f - wx1;

    bool vy0 = (y0 >= 0) & (y0 < H), vy1 = (y1 >= 0) & (y1 < H);
    bool vx0 = (x0 >= 0) & (x0 < W), vx1 = (x1 >= 0) & (x1 < W);
    int yc0 = min(max(y0, 0), H - 1), yc1 = min(max(y1, 0), H - 1);
    int xc0 = min(max(x0, 0), W - 1), xc1 = min(max(x1, 0), W - 1);

    float w00 = wy0 * wx0 * ((vy0 & vx0) ? m : 0.f);
    float w01 = wy0 * wx1 * ((vy0 & vx1) ? m : 0.f);
    float w10 = wy1 * wx0 * ((vy1 & vx0) ? m : 0.f);
    float w11 = wy1 * wx1 * ((vy1 & vx1) ? m : 0.f);

    int i00 = yc0 * W + xc0, i01 = yc0 * W + xc1;
    int i10 = yc1 * W + xc0, i11 = yc1 * W + xc1;

    const float* xb = x + (size_t)b * CIN * HW;
    size_t base = (size_t)b * GK * HW + (size_t)k * HW + p;
#pragma unroll 4
    for (int c = 0; c < CIN; c++) {
        const float* xc = xb + (size_t)c * HW;
        float v = w00 * __ldg(xc + i00) + w01 * __ldg(xc + i01)
                + w10 * __ldg(xc + i10) + w11 * __ldg(xc + i11);
        __half hi = __float2half_rn(v);
        __half lo = __float2half_rn(v - __half2float(hi));
        size_t idx = base + (size_t)c * KK * HW;
        chi[idx] = hi;
        clo[idx] = lo;
    }
}

// ---------------- weight split fp32 -> fp16 hi/lo -----------------------------
__global__ void wsplit_kernel(const float* __restrict__ w,
                              __half* __restrict__ whi,
                              __half* __restrict__ wlo) {
    int i = blockIdx.x * 256 + threadIdx.x;      // GM*GK multiple of 256
    float v = w[i];
    __half hi = __float2half_rn(v);
    whi[i] = hi;
    wlo[i] = __float2half_rn(v - __half2float(hi));
}

// ---------------- fp16 split GEMM + ReLU --------------------------------------
// C[b][o][p] = relu( sum_k W[o][k] * col[b][k][p] ), 3-term hi/lo split.
// grid (GN/128, GM/128, B), block 256 (8 warps), tile 128x128x64, double-buffered.
#define NCH (GK / 64)                 // 36
// per-stage smem layout (bytes): AH 16K | AL 16K | BH 16K | BL 16K  = 64K
#define STG_AH 0
#define STG_AL 16384
#define STG_BH 32768
#define STG_BL 49152
#define STG_SIZE 65536
#define SM_BYTES (2 * STG_SIZE)       // 128 KB

__device__ __forceinline__ void load_stage(uint32_t sb, int k0, int tid,
                                           const __half* Ah, const __half* Al,
                                           const __half* Bh, const __half* Bl) {
    // A planes: 128 rows x 8 chunks(16B); thread -> row = tid&127, 4 chunks
    {
        int row = tid & 127;
        int c0 = (tid >> 7) * 4;
        const __half* sh = Ah + (size_t)row * GK + k0;
        const __half* sl = Al + (size_t)row * GK + k0;
        uint32_t rbase = sb + (uint32_t)row * 128;
#pragma unroll
        for (int j = 0; j < 4; j++) {
            int c = c0 + j;
            uint32_t d = rbase + (uint32_t)((c ^ (row & 7)) << 4);
            cpasync16(d + STG_AH, sh + c * 8);
            cpasync16(d + STG_AL, sl + c * 8);
        }
    }
    // B planes: 64 rows x 16 chunks; thread -> row = tid&63, 4 chunks
    {
        int row = tid & 63;
        int c0 = (tid >> 6) * 4;
        const __half* sh = Bh + (size_t)(k0 + row) * GN;
        const __half* sl = Bl + (size_t)(k0 + row) * GN;
        uint32_t rbase = sb + (uint32_t)row * 256;
#pragma unroll
        for (int j = 0; j < 4; j++) {
            int c = c0 + j;
            uint32_t d = rbase + (uint32_t)((c ^ (row & 7)) << 4);
            cpasync16(d + STG_BH, sh + c * 8);
            cpasync16(d + STG_BL, sl + c * 8);
        }
    }
}

__global__ __launch_bounds__(256, 1)
void gemm_f16s_kernel(const __half* __restrict__ whi,
                      const __half* __restrict__ wlo,
                      const __half* __restrict__ chi,
                      const __half* __restrict__ clo,
                      float* __restrict__ Cc) {
    extern __shared__ char smc[];
    uint32_t smb = sm_u32(smc);
    const int tid = threadIdx.x;
    const int lane = tid & 31;
    const int wrp = tid >> 5;
    const int b = blockIdx.z;
    const int p0 = blockIdx.x * 128;
    const int m0 = blockIdx.y * 128;

    const __half* Ah = whi + (size_t)m0 * GK;
    const __half* Al = wlo + (size_t)m0 * GK;
    const __half* Bh = chi + (size_t)b * GK * GN + p0;
    const __half* Bl = clo + (size_t)b * GK * GN + p0;

    // prologue: chunks 0,1
    load_stage(smb, 0, tid, Ah, Al, Bh, Bl);
    CP_COMMIT();
    load_stage(smb + STG_SIZE, 64, tid, Ah, Al, Bh, Bl);
    CP_COMMIT();

    const int wm = (wrp >> 2) * 64;
    const int wn = (wrp & 3) * 32;
    const int t8 = lane >> 3, r8 = lane & 7;
    const int ar = lane >> 2, ac = lane & 3;

    float acc[4][4][4];
#pragma unroll
    for (int i = 0; i < 4; i++)
#pragma unroll
        for (int j = 0; j < 4; j++)
#pragma unroll
            for (int q = 0; q < 4; q++) acc[i][j][q] = 0.f;

    for (int ch = 0; ch < NCH; ch++) {
        CP_WAIT1();
        __syncthreads();
        uint32_t sb = smb + (uint32_t)(ch & 1) * STG_SIZE;

#pragma unroll
        for (int ks = 0; ks < 4; ks++) {
            // A fragments (hi & lo), mf = 0..3
            uint32_t ah[4][4], al[4][4];
#pragma unroll
            for (int mf = 0; mf < 4; mf++) {
                int mrow = wm + mf * 16 + r8 + 8 * (t8 & 1);
                int chk = 2 * ks + (t8 >> 1);
                uint32_t off = (uint32_t)mrow * 128 + (uint32_t)((chk ^ (mrow & 7)) << 4);
                LDSM_X4(ah[mf][0], ah[mf][1], ah[mf][2], ah[mf][3], sb + STG_AH + off);
                LDSM_X4(al[mf][0], al[mf][1], al[mf][2], al[mf][3], sb + STG_AL + off);
            }
            // B fragments (hi & lo), np = 0..1 covers nf pairs
            uint32_t bh[2][4], bl[2][4];
#pragma unroll
            for (int np = 0; np < 2; np++) {
                int krow = 16 * ks + r8 + 8 * (t8 & 1);
                int chk = (wn >> 3) + np * 2 + (t8 >> 1);
                uint32_t off = (uint32_t)krow * 256 + (uint32_t)((chk ^ (krow & 7)) << 4);
                LDSM_X4_T(bh[np][0], bh[np][1], bh[np][2], bh[np][3], sb + STG_BH + off);
                LDSM_X4_T(bl[np][0], bl[np][1], bl[np][2], bl[np][3], sb + STG_BL + off);
            }
#pragma unroll
            for (int mf = 0; mf < 4; mf++)
#pragma unroll
                for (int nf = 0; nf < 4; nf++) {
                    uint32_t* bhf = &bh[nf >> 1][(nf & 1) * 2];
                    uint32_t* blf = &bl[nf >> 1][(nf & 1) * 2];
                    MMA_F16(acc[mf][nf], ah[mf], bhf);
                    MMA_F16(acc[mf][nf], ah[mf], blf);
                    MMA_F16(acc[mf][nf], al[mf], bhf);
                }
        }
        __syncthreads();

        if (ch + 2 < NCH)
            load_stage(smb + (uint32_t)(ch & 1) * STG_SIZE, (ch + 2) * 64, tid,
                       Ah, Al, Bh, Bl);
        CP_COMMIT();
    }

    // epilogue: ReLU + float2 stores
    float* Cb = Cc + (size_t)b * GM * GN;
    const int obase = m0 + wm;
    const int pbase = p0 + wn;
#pragma unroll
    for (int mf = 0; mf < 4; mf++) {
#pragma unroll
        for (int nf = 0; nf < 4; nf++) {
            int o = obase + mf * 16 + ar;
            int p = pbase + nf * 8 + 2 * ac;
            float2 v0, v1;
            v0.x = fmaxf(acc[mf][nf][0], 0.f);
            v0.y = fmaxf(acc[mf][nf][1], 0.f);
            v1.x = fmaxf(acc[mf][nf][2], 0.f);
            v1.y = fmaxf(acc[mf][nf][3], 0.f);
            *(float2*)(Cb + (size_t)o * GN + p) = v0;
            *(float2*)(Cb + (size_t)(o + 8) * GN + p) = v1;
        }
    }
}

// ---------------- host side ----------------------------------------------------
static void run_layer(const float* xin, const float* w_off, const float* b_off,
                      const float* wmain, float* outp,
                      __half* chi, __half* clo, float* om, float* om_part,
                      __half* whi, __half* wlo) {
    dim3 gOff(36, 4, B);
    offset_conv_kernel<<<gOff, 256>>>(xin, w_off, om_part);
    reduce_om_kernel<<<(B * 27 * HW) / 256, 256>>>(om_part, b_off, om);
    wsplit_kernel<<<(GM * GK) / 256, 256>>>(wmain, whi, wlo);
    dim3 gSamp(36, KK, B);
    sample_kernel<<<gSamp, 256>>>(xin, om, chi, clo);
    dim3 gGemm(GN / 128, GM / 128, B);
    gemm_f16s_kernel<<<gGemm, 256, SM_BYTES>>>(whi, wlo, chi, clo, outp);
}

extern "C" void kernel_launch(void* const* d_in, const int* in_sizes, int n_in,
                              void* d_out, int out_size) {
    const float* x      = (const float*)d_in[0];
    const float* w_off0 = (const float*)d_in[1];
    const float* b_off0 = (const float*)d_in[2];
    const float* w0     = (const float*)d_in[3];
    const float* w_off1 = (const float*)d_in[4];
    const float* b_off1 = (const float*)d_in[5];
    const float* w1     = (const float*)d_in[6];
    float* out = (float*)d_out;

    static bool attr_set = false;
    if (!attr_set) {
        cudaFuncSetAttribute(gemm_f16s_kernel,
                             cudaFuncAttributeMaxDynamicSharedMemorySize, SM_BYTES);
        attr_set = true;
    }

    __half *chi, *clo, *whi, *wlo;
    float *om, *om_part, *hbuf;
    cudaGetSymbolAddress((void**)&chi,     g_colhi);
    cudaGetSymbolAddress((void**)&clo,     g_collo);
    cudaGetSymbolAddress((void**)&om,      g_om);
    cudaGetSymbolAddress((void**)&om_part, g_om_part);
    cudaGetSymbolAddress((void**)&hbuf,    g_h);
    cudaGetSymbolAddress((void**)&whi,     g_whi);
    cudaGetSymbolAddress((void**)&wlo,     g_wlo);

    run_layer(x,    w_off0, b_off0, w0, hbuf, chi, clo, om, om_part, whi, wlo);
    run_layer(hbuf, w_off1, b_off1, w1, out,  chi, clo, om, om_part, whi, wlo);
}

// round 6
// speedup vs baseline: 1.2196x; 1.2196x over previous
#include <cuda_runtime.h>
#include <cuda_fp16.h>
#include <math.h>
#include <stdint.h>

#define H 96
#define W 96
#define HW (H*W)          // 9216
#define CIN 256
#define B 2
#define KK 9
#define GK (CIN*KK)       // 2304
#define GM 256
#define GN HW

// ---------------- scratch (static device allocations) -------------------------
__device__ __half g_colhi[(size_t)B * GK * HW];     // im2col hi plane [b][k][p]
__device__ __half g_collo[(size_t)B * GK * HW];     // im2col lo plane
__device__ float g_om[(size_t)B * 27 * HW];
__device__ float g_om_part[4ull * B * 27 * HW];
__device__ float g_h[(size_t)B * CIN * HW];
__device__ __half g_whi[(size_t)GM * GK];           // W hi [o][k]
__device__ __half g_wlo[(size_t)GM * GK];           // W lo

// ---------------- helpers ------------------------------------------------------
__device__ __forceinline__ uint32_t sm_u32(const void* p) {
    uint32_t a;
    asm("{ .reg .u64 t; cvta.to.shared.u64 t, %1; cvt.u32.u64 %0, t; }" : "=r"(a) : "l"(p));
    return a;
}
__device__ __forceinline__ void cpasync16(uint32_t dst, const void* src) {
    asm volatile("cp.async.cg.shared.global [%0], [%1], 16;" :: "r"(dst), "l"(src));
}
#define CP_COMMIT() asm volatile("cp.async.commit_group;" ::: "memory")
#define CP_WAIT1()  asm volatile("cp.async.wait_group 1;" ::: "memory")

#define LDSM_X4(r0, r1, r2, r3, addr) \
    asm volatile("ldmatrix.sync.aligned.m8n8.x4.shared.b16 {%0,%1,%2,%3}, [%4];" \
        : "=r"(r0), "=r"(r1), "=r"(r2), "=r"(r3) : "r"(addr))
#define LDSM_X4_T(r0, r1, r2, r3, addr) \
    asm volatile("ldmatrix.sync.aligned.m8n8.x4.trans.shared.b16 {%0,%1,%2,%3}, [%4];" \
        : "=r"(r0), "=r"(r1), "=r"(r2), "=r"(r3) : "r"(addr))

#define MMA_F16(d, a, bb) \
    asm volatile("mma.sync.aligned.m16n8k16.row.col.f32.f16.f16.f32 " \
        "{%0,%1,%2,%3}, {%4,%5,%6,%7}, {%8,%9}, {%0,%1,%2,%3};" \
        : "+f"((d)[0]), "+f"((d)[1]), "+f"((d)[2]), "+f"((d)[3]) \
        : "r"((a)[0]), "r"((a)[1]), "r"((a)[2]), "r"((a)[3]), \
          "r"((bb)[0]), "r"((bb)[1]))

// ---------------- offset conv (SMEM-tiled): grid (36,4,B), block 256 ----------
__global__ void offset_conv_kernel(const float* __restrict__ x,
                                   const float* __restrict__ w_off,
                                   float* __restrict__ om_part) {
    int b = blockIdx.z, chunk = blockIdx.y, tile = blockIdx.x;
    int h0 = (tile / 6) * 16, w0 = (tile % 6) * 16;
    int ty = threadIdx.x >> 4, tx = threadIdx.x & 15;

    float acc[27];
#pragma unroll
    for (int i = 0; i < 27; i++) acc[i] = 0.f;

    __shared__ float ws[243];
    __shared__ float xt[18 * 18];
    const float* xb = x + (size_t)b * CIN * HW;
    int c0 = chunk * 64;
    for (int c = c0; c < c0 + 64; c++) {
        __syncthreads();
        if (threadIdx.x < 243) {
            int oc = threadIdx.x / 9, k = threadIdx.x % 9;
            ws[threadIdx.x] = w_off[((size_t)oc * CIN + c) * 9 + k];
        }
        const float* xc = xb + (size_t)c * HW;
        for (int idx = threadIdx.x; idx < 324; idx += 256) {
            int yy = h0 - 1 + idx / 18, xx = w0 - 1 + idx % 18;
            xt[idx] = (yy >= 0 && yy < H && xx >= 0 && xx < W) ? xc[yy * W + xx] : 0.f;
        }
        __syncthreads();
        float xv[9];
#pragma unroll
        for (int k = 0; k < 9; k++)
            xv[k] = xt[(ty + k / 3) * 18 + tx + k % 3];
#pragma unroll
        for (int oc = 0; oc < 27; oc++)
#pragma unroll
            for (int k = 0; k < 9; k++)
                acc[oc] = fmaf(ws[oc * 9 + k], xv[k], acc[oc]);
    }
    int h = h0 + ty, w = w0 + tx;
    float* dst = om_part + ((size_t)chunk * B * 27 + (size_t)b * 27) * HW + h * W + w;
#pragma unroll
    for (int oc = 0; oc < 27; oc++) dst[(size_t)oc * HW] = acc[oc];
}

__global__ void reduce_om_kernel(const float* __restrict__ part,
                                 const float* __restrict__ b_off,
                                 float* __restrict__ om) {
    int i = blockIdx.x * 256 + threadIdx.x;
    const int N = B * 27 * HW;
    int oc = (i / HW) % 27;
    float s = b_off[oc];
#pragma unroll
    for (int j = 0; j < 4; j++) s += part[(size_t)j * N + i];
    om[i] = s;
}

// ---------------- deformable im2col -> fp16 hi/lo planes ----------------------
// grid (36, 9*4, B): y encodes (cchunk, k); each block does 64 channels
__global__ void sample_kernel(const float* __restrict__ x,
                              const float* __restrict__ om,
                              __half* __restrict__ chi,
                              __half* __restrict__ clo) {
    int b = blockIdx.z;
    int k = blockIdx.y % KK;
    int cc = blockIdx.y / KK;
    int p = blockIdx.x * 256 + threadIdx.x;
    int h = p / W, w = p % W;

    const float* omb = om + (size_t)b * 27 * HW;
    float dy = omb[(size_t)(2 * k) * HW + p];
    float dx = omb[(size_t)(2 * k + 1) * HW + p];
    float m  = omb[(size_t)(18 + k) * HW + p];
    m = 1.f / (1.f + __expf(-m));

    float ys = (float)(h + k / 3 - 1) + dy;
    float xs = (float)(w + k % 3 - 1) + dx;
    float y0f = floorf(ys), x0f = floorf(xs);
    int y0 = (int)y0f, x0 = (int)x0f;
    int y1 = y0 + 1, x1 = x0 + 1;
    float wy1 = ys - y0f, wx1 = xs - x0f;
    float wy0 = 1.f - wy1, wx0 = 1.f - wx1;

    bool vy0 = (y0 >= 0) & (y0 < H), vy1 = (y1 >= 0) & (y1 < H);
    bool vx0 = (x0 >= 0) & (x0 < W), vx1 = (x1 >= 0) & (x1 < W);
    int yc0 = min(max(y0, 0), H - 1), yc1 = min(max(y1, 0), H - 1);
    int xc0 = min(max(x0, 0), W - 1), xc1 = min(max(x1, 0), W - 1);

    float w00 = wy0 * wx0 * ((vy0 & vx0) ? m : 0.f);
    float w01 = wy0 * wx1 * ((vy0 & vx1) ? m : 0.f);
    float w10 = wy1 * wx0 * ((vy1 & vx0) ? m : 0.f);
    float w11 = wy1 * wx1 * ((vy1 & vx1) ? m : 0.f);

    int i00 = yc0 * W + xc0, i01 = yc0 * W + xc1;
    int i10 = yc1 * W + xc0, i11 = yc1 * W + xc1;

    const float* xb = x + (size_t)b * CIN * HW;
    size_t base = (size_t)b * GK * HW + (size_t)k * HW + p;
    int cbeg = cc * 64, cend = cbeg + 64;
#pragma unroll 8
    for (int c = cbeg; c < cend; c++) {
        const float* xc = xb + (size_t)c * HW;
        float v = w00 * __ldg(xc + i00) + w01 * __ldg(xc + i01)
                + w10 * __ldg(xc + i10) + w11 * __ldg(xc + i11);
        __half hi = __float2half_rn(v);
        __half lo = __float2half_rn(v - __half2float(hi));
        size_t idx = base + (size_t)c * KK * HW;
        chi[idx] = hi;
        clo[idx] = lo;
    }
}

// ---------------- weight split fp32 -> fp16 hi/lo -----------------------------
__global__ void wsplit_kernel(const float* __restrict__ w,
                              __half* __restrict__ whi,
                              __half* __restrict__ wlo) {
    int i = blockIdx.x * 256 + threadIdx.x;
    float v = w[i];
    __half hi = __float2half_rn(v);
    whi[i] = hi;
    wlo[i] = __float2half_rn(v - __half2float(hi));
}

// ---------------- fp16 split GEMM + ReLU --------------------------------------
// C[b][o][p] = relu( sum_k W[o][k] * col[b][k][p] ), 3-term hi/lo split.
// CTA tile M=256 (full GM), N=128 pixels, K-chunk 32, double-buffered.
// grid (GN/128, 1, B) = 72 x 2 = 144 CTAs = 1 wave. 8 warps, warp tile 64x64.
#define NCH (GK / 32)                 // 72
#define STG_AH 0                      // 256 rows x 64B = 16 KB
#define STG_AL 16384
#define STG_BH 32768                  // 32 rows x 256B = 8 KB
#define STG_BL 40960
#define STG_SIZE 49152
#define SM_BYTES (2 * STG_SIZE)       // 96 KB

__device__ __forceinline__ void load_stage(uint32_t sb, int k0, int tid,
                                           const __half* Ah, const __half* Al,
                                           const __half* Bh, const __half* Bl) {
    // A: 256 rows (o) x 32 k (64B = 4 chunks). thread -> row = tid, chunks 0..3
    {
        int row = tid;
        const __half* sh = Ah + (size_t)row * GK + k0;
        const __half* sl = Al + (size_t)row * GK + k0;
        uint32_t rbase = sb + (uint32_t)row * 64;
        uint32_t sw = (uint32_t)((row >> 1) & 3);
#pragma unroll
        for (int j = 0; j < 4; j++) {
            uint32_t d = rbase + (uint32_t)((j ^ sw) << 4);
            cpasync16(d + STG_AH, sh + j * 8);
            cpasync16(d + STG_AL, sl + j * 8);
        }
    }
    // B: 32 rows (k) x 128 p (256B = 16 chunks). thread -> row = tid>>3, 2 chunks
    {
        int row = tid >> 3;
        int c0 = tid & 7;
        const __half* sh = Bh + (size_t)(k0 + row) * GN;
        const __half* sl = Bl + (size_t)(k0 + row) * GN;
        uint32_t rbase = sb + (uint32_t)row * 256;
        uint32_t sw = (uint32_t)(row & 7);
#pragma unroll
        for (int j = 0; j < 2; j++) {
            int c = c0 + j * 8;
            uint32_t d = rbase + (uint32_t)((c ^ sw) << 4);
            cpasync16(d + STG_BH, sh + c * 8);
            cpasync16(d + STG_BL, sl + c * 8);
        }
    }
}

__global__ __launch_bounds__(256, 1)
void gemm_f16s_kernel(const __half* __restrict__ whi,
                      const __half* __restrict__ wlo,
                      const __half* __restrict__ chi,
                      const __half* __restrict__ clo,
                      float* __restrict__ Cc) {
    extern __shared__ char smc[];
    uint32_t smb = sm_u32(smc);
    const int tid = threadIdx.x;
    const int lane = tid & 31;
    const int wrp = tid >> 5;
    const int b = blockIdx.z;
    const int p0 = blockIdx.x * 128;

    const __half* Ah = whi;
    const __half* Al = wlo;
    const __half* Bh = chi + (size_t)b * GK * GN + p0;
    const __half* Bl = clo + (size_t)b * GK * GN + p0;

    load_stage(smb, 0, tid, Ah, Al, Bh, Bl);
    CP_COMMIT();
    load_stage(smb + STG_SIZE, 32, tid, Ah, Al, Bh, Bl);
    CP_COMMIT();

    const int wm = (wrp >> 1) * 64;   // warp m offset: 0,64,128,192
    const int wn8 = (wrp & 1) * 8;    // warp n offset in 16B chunks (64 halves)
    const int t8 = lane >> 3, r8 = lane & 7;
    const int ar = lane >> 2, ac = lane & 3;

    float acc[4][8][4];
#pragma unroll
    for (int i = 0; i < 4; i++)
#pragma unroll
        for (int j = 0; j < 8; j++)
#pragma unroll
            for (int q = 0; q < 4; q++) acc[i][j][q] = 0.f;

    for (int ch = 0; ch < NCH; ch++) {
        CP_WAIT1();
        __syncthreads();
        uint32_t sb = smb + (uint32_t)(ch & 1) * STG_SIZE;

#pragma unroll
        for (int ks = 0; ks < 2; ks++) {
            uint32_t ah[4][4], al[4][4];
#pragma unroll
            for (int mf = 0; mf < 4; mf++) {
                int mrow = wm + mf * 16 + r8 + 8 * (t8 & 1);
                int chk = 2 * ks + (t8 >> 1);
                uint32_t off = (uint32_t)mrow * 64 +
                               (uint32_t)((chk ^ ((mrow >> 1) & 3)) << 4);
                LDSM_X4(ah[mf][0], ah[mf][1], ah[mf][2], ah[mf][3], sb + STG_AH + off);
                LDSM_X4(al[mf][0], al[mf][1], al[mf][2], al[mf][3], sb + STG_AL + off);
            }
#pragma unroll
            for (int np = 0; np < 4; np++) {
                uint32_t bh[4], bl[4];
                int krow = 16 * ks + r8 + 8 * (t8 & 1);
                int chkb = wn8 + np * 2 + (t8 >> 1);
                uint32_t off = (uint32_t)krow * 256 +
                               (uint32_t)((chkb ^ (krow & 7)) << 4);
                LDSM_X4_T(bh[0], bh[1], bh[2], bh[3], sb + STG_BH + off);
                LDSM_X4_T(bl[0], bl[1], bl[2], bl[3], sb + STG_BL + off);
#pragma unroll
                for (int mf = 0; mf < 4; mf++)
#pragma unroll
                    for (int s = 0; s < 2; s++) {
                        float* d = acc[mf][np * 2 + s];
                        MMA_F16(d, ah[mf], &bh[s * 2]);
                        MMA_F16(d, ah[mf], &bl[s * 2]);
                        MMA_F16(d, al[mf], &bh[s * 2]);
                    }
            }
        }
        __syncthreads();

        if (ch + 2 < NCH)
            load_stage(smb + (uint32_t)(ch & 1) * STG_SIZE, (ch + 2) * 32, tid,
                       Ah, Al, Bh, Bl);
        CP_COMMIT();
    }

    // epilogue: ReLU + float2 stores
    float* Cb = Cc + (size_t)b * GM * GN;
    const int pb = p0 + (wrp & 1) * 64;
#pragma unroll
    for (int mf = 0; mf < 4; mf++) {
#pragma unroll
        for (int nf = 0; nf < 8; nf++) {
            int o = wm + mf * 16 + ar;
            int p = pb + nf * 8 + 2 * ac;
            float2 v0, v1;
            v0.x = fmaxf(acc[mf][nf][0], 0.f);
            v0.y = fmaxf(acc[mf][nf][1], 0.f);
            v1.x = fmaxf(acc[mf][nf][2], 0.f);
            v1.y = fmaxf(acc[mf][nf][3], 0.f);
            *(float2*)(Cb + (size_t)o * GN + p) = v0;
            *(float2*)(Cb + (size_t)(o + 8) * GN + p) = v1;
        }
    }
}

// ---------------- host side ----------------------------------------------------
static void run_layer(const float* xin, const float* w_off, const float* b_off,
                      const float* wmain, float* outp,
                      __half* chi, __half* clo, float* om, float* om_part,
                      __half* whi, __half* wlo) {
    dim3 gOff(36, 4, B);
    offset_conv_kernel<<<gOff, 256>>>(xin, w_off, om_part);
    reduce_om_kernel<<<(B * 27 * HW) / 256, 256>>>(om_part, b_off, om);
    wsplit_kernel<<<(GM * GK) / 256, 256>>>(wmain, whi, wlo);
    dim3 gSamp(36, KK * 4, B);
    sample_kernel<<<gSamp, 256>>>(xin, om, chi, clo);
    dim3 gGemm(GN / 128, 1, B);
    gemm_f16s_kernel<<<gGemm, 256, SM_BYTES>>>(whi, wlo, chi, clo, outp);
}

extern "C" void kernel_launch(void* const* d_in, const int* in_sizes, int n_in,
                              void* d_out, int out_size) {
    const float* x      = (const float*)d_in[0];
    const float* w_off0 = (const float*)d_in[1];
    const float* b_off0 = (const float*)d_in[2];
    const float* w0     = (const float*)d_in[3];
    const float* w_off1 = (const float*)d_in[4];
    const float* b_off1 = (const float*)d_in[5];
    const float* w1     = (const float*)d_in[6];
    float* out = (float*)d_out;

    static bool attr_set = false;
    if (!attr_set) {
        cudaFuncSetAttribute(gemm_f16s_kernel,
                             cudaFuncAttributeMaxDynamicSharedMemorySize, SM_BYTES);
        attr_set = true;
    }

    __half *chi, *clo, *whi, *wlo;
    float *om, *om_part, *hbuf;
    cudaGetSymbolAddress((void**)&chi,     g_colhi);
    cudaGetSymbolAddress((void**)&clo,     g_collo);
    cudaGetSymbolAddress((void**)&om,      g_om);
    cudaGetSymbolAddress((void**)&om_part, g_om_part);
    cudaGetSymbolAddress((void**)&hbuf,    g_h);
    cudaGetSymbolAddress((void**)&whi,     g_whi);
    cudaGetSymbolAddress((void**)&wlo,     g_wlo);

    run_layer(x,    w_off0, b_off0, w0, hbuf, chi, clo, om, om_part, whi, wlo);
    run_layer(hbuf, w_off1, b_off1, w1, out,  chi, clo, om, om_part, whi, wlo);
}